// round 3
// baseline (speedup 1.0000x reference)
#include <cuda_runtime.h>
#include <math.h>

// Problem constants (fixed by the reference: B=64, P=1024, D=768)
#define Bsz   64
#define Pseq  1024
#define Ddim  768
#define RTOT  (Bsz * Pseq)            // 65536 total rows
#define NCTA  148                     // one CTA per SM, full wave
#define NWARPS 16
#define NTHREADS (NWARPS * 32)        // 512
#define DPL (Ddim / 32)               // 24 d-elements per lane
#define SLOTS (2 * NCTA)              // <=2 batch-partials per CTA

#define QE  16                        // e-rows per qw-partial chunk
#define QNC (Ddim / QE)               // 48 chunks

// Scratch (no cudaMalloc allowed) -------------------------------------------
__device__ float g_qw_part[QNC][Ddim];
__device__ float g_qw[Ddim];
__device__ float g_pm[SLOTS];
__device__ float g_pl[SLOTS];
__device__ int   g_ptag[SLOTS];
__device__ float g_pacc[SLOTS * Ddim];

// Kernel 1a: partial qw, vectorized. grid=QNC, block=192 (each thread owns 4 d)
__global__ void qw_part_kernel(const float* __restrict__ q,
                               const float* __restrict__ W) {
    const int d4 = threadIdx.x * 4;
    const int e0 = blockIdx.x * QE;
    float4 acc = make_float4(0.f, 0.f, 0.f, 0.f);
#pragma unroll
    for (int i = 0; i < QE; ++i) {
        const float qv = __ldg(&q[e0 + i]);
        const float4 w = *reinterpret_cast<const float4*>(&W[(long)(e0 + i) * Ddim + d4]);
        acc.x += qv * w.x; acc.y += qv * w.y;
        acc.z += qv * w.z; acc.w += qv * w.w;
    }
    *reinterpret_cast<float4*>(&g_qw_part[blockIdx.x][d4]) = acc;
}

// Kernel 1b: fold QNC partials into g_qw (L2-hot). grid=1, block=192
__global__ void qw_reduce_kernel() {
    const int d4 = threadIdx.x * 4;
    float4 acc = make_float4(0.f, 0.f, 0.f, 0.f);
#pragma unroll
    for (int c = 0; c < QNC; ++c) {
        const float4 v = *reinterpret_cast<const float4*>(&g_qw_part[c][d4]);
        acc.x += v.x; acc.y += v.y; acc.z += v.z; acc.w += v.w;
    }
    const float s = rsqrtf((float)Ddim);
    acc.x *= s; acc.y *= s; acc.z *= s; acc.w *= s;
    *reinterpret_cast<float4*>(&g_qw[d4]) = acc;
}

// Kernel 2: flattened-row online-softmax partials ------------------------------
// 148 CTAs cover all 65536 rows evenly; each CTA spans <=2 batches and emits
// up to 2 tagged partial states (slots 2*bid, 2*bid+1).
__device__ __forceinline__ void load_row(const float* __restrict__ zr, int lane,
                                         float v[DPL]) {
#pragma unroll
    for (int i = 0; i < 6; ++i) {
        float4 t = *reinterpret_cast<const float4*>(&zr[i * 128 + lane * 4]);
        v[i * 4 + 0] = t.x; v[i * 4 + 1] = t.y;
        v[i * 4 + 2] = t.z; v[i * 4 + 3] = t.w;
    }
}

extern __shared__ float smem[];
__global__ __launch_bounds__(NTHREADS)
void attn_partial_kernel(const float* __restrict__ z) {
    float* qw_s  = smem;                     // [Ddim]
    float* acc_s = smem + Ddim;              // [NWARPS * Ddim]
    float* m_s   = acc_s + NWARPS * Ddim;    // [NWARPS]
    float* l_s   = m_s + NWARPS;             // [NWARPS]

    const int bid  = blockIdx.x;
    const int tid  = threadIdx.x;
    const int w    = tid >> 5;
    const int lane = tid & 31;

    for (int t = tid; t < Ddim; t += NTHREADS) qw_s[t] = g_qw[t];
    __syncthreads();

    float qw_r[DPL];
    load_row(qw_s, lane, qw_r);

    // This CTA's contiguous row range, split evenly among warps
    const int start = (int)(((long)bid * RTOT) / NCTA);
    const int end   = (int)(((long)(bid + 1) * RTOT) / NCTA);
    const int cnt   = end - start;
    const int ws    = start + (int)(((long)w * cnt) / NWARPS);
    const int we    = start + (int)(((long)(w + 1) * cnt) / NWARPS);
    const int bstart = start >> 10;           // Pseq = 1024 = 2^10
    const int bend   = (end - 1) >> 10;

#pragma unroll 1
    for (int pass = 0; pass < 2; ++pass) {
        int bb = (pass == 0) ? bstart : ((bend != bstart) ? bend : -1);
        int lo = ws, hi = we;
        if (bb >= 0) {
            lo = max(ws, bb << 10);
            hi = min(we, (bb + 1) << 10);
        } else { lo = 0; hi = 0; }

        float m = -INFINITY, l = 0.f;
        float acc[DPL];
#pragma unroll
        for (int j = 0; j < DPL; ++j) acc[j] = 0.f;

        if (lo < hi) {
            float cv[DPL];
            load_row(z + (long)lo * Ddim, lane, cv);
            for (int g = lo; g < hi; ++g) {
                float nv[DPL];
                if (g + 1 < hi) load_row(z + (long)(g + 1) * Ddim, lane, nv);

                float sc = 0.f;
#pragma unroll
                for (int j = 0; j < DPL; ++j) sc += cv[j] * qw_r[j];
#pragma unroll
                for (int o = 16; o; o >>= 1)
                    sc += __shfl_xor_sync(0xffffffffu, sc, o);

                float m_new = fmaxf(m, sc);
                float alpha = __expf(m - m_new);
                float wp    = __expf(sc - m_new);
                l = l * alpha + wp;
#pragma unroll
                for (int j = 0; j < DPL; ++j) acc[j] = acc[j] * alpha + wp * cv[j];
                m = m_new;
#pragma unroll
                for (int j = 0; j < DPL; ++j) cv[j] = nv[j];
            }
        }

        // Stage per-warp state
#pragma unroll
        for (int i = 0; i < 6; ++i) {
            float4 v = make_float4(acc[i * 4 + 0], acc[i * 4 + 1],
                                   acc[i * 4 + 2], acc[i * 4 + 3]);
            *reinterpret_cast<float4*>(&acc_s[w * Ddim + i * 128 + lane * 4]) = v;
        }
        if (lane == 0) { m_s[w] = m; l_s[w] = l; }
        __syncthreads();

        // CTA combine -> global slot 2*bid+pass
        float M = -INFINITY;
#pragma unroll
        for (int ww = 0; ww < NWARPS; ++ww) M = fmaxf(M, m_s[ww]);

        const int slot = 2 * bid + pass;
        if (M == -INFINITY) {
            if (tid == 0) { g_ptag[slot] = -1; g_pm[slot] = 0.f; g_pl[slot] = 1.f; }
        } else {
            float ew[NWARPS];
#pragma unroll
            for (int ww = 0; ww < NWARPS; ++ww) ew[ww] = __expf(m_s[ww] - M);
            for (int t = tid; t < Ddim; t += NTHREADS) {
                float sum = 0.f;
#pragma unroll
                for (int ww = 0; ww < NWARPS; ++ww)
                    sum += ew[ww] * acc_s[ww * Ddim + t];
                g_pacc[slot * Ddim + t] = sum;
            }
            if (tid == 0) {
                float L = 0.f;
#pragma unroll
                for (int ww = 0; ww < NWARPS; ++ww) L += ew[ww] * l_s[ww];
                g_pm[slot] = M; g_pl[slot] = L; g_ptag[slot] = bb;
            }
        }
        __syncthreads();   // protect smem reuse in pass 1
    }
}

// Kernel 3: gather tagged partials per batch, normalize, write output ---------
__global__ void combine_kernel(float* __restrict__ out) {
    const int b = blockIdx.x;
    const int t = threadIdx.x;  // 0..Ddim-1

    __shared__ float sm[SLOTS], sl[SLOTS];
    __shared__ int   st[SLOTS];
    if (t < SLOTS) { st[t] = g_ptag[t]; sm[t] = g_pm[t]; sl[t] = g_pl[t]; }
    __syncthreads();

    float M = -INFINITY;
    for (int s = 0; s < SLOTS; ++s)
        if (st[s] == b) M = fmaxf(M, sm[s]);

    float L = 0.f, num = 0.f;
    for (int s = 0; s < SLOTS; ++s) {
        if (st[s] == b) {
            float e = __expf(sm[s] - M);
            L   += e * sl[s];
            num += e * g_pacc[s * Ddim + t];
        }
    }
    out[b * Ddim + t] = num / L;
}

// ----------------------------------------------------------------------------
extern "C" void kernel_launch(void* const* d_in, const int* in_sizes, int n_in,
                              void* d_out, int out_size) {
    const float* z = nullptr; const float* q = nullptr; const float* W = nullptr;
    for (int i = 0; i < n_in; ++i) {
        if (in_sizes[i] == Bsz * Pseq * Ddim)      z = (const float*)d_in[i];
        else if (in_sizes[i] == Ddim)              q = (const float*)d_in[i];
        else if (in_sizes[i] == Ddim * Ddim)       W = (const float*)d_in[i];
    }
    float* out = (float*)d_out;

    const int smem_bytes = (Ddim + NWARPS * Ddim + 2 * NWARPS) * (int)sizeof(float);
    cudaFuncSetAttribute(attn_partial_kernel,
                         cudaFuncAttributeMaxDynamicSharedMemorySize, smem_bytes);

    qw_part_kernel<<<QNC, Ddim / 4>>>(q, W);
    qw_reduce_kernel<<<1, Ddim / 4>>>();
    attn_partial_kernel<<<NCTA, NTHREADS, smem_bytes>>>(z);
    combine_kernel<<<Bsz, Ddim>>>(out);
}

// round 4
// speedup vs baseline: 1.2023x; 1.2023x over previous
#include <cuda_runtime.h>
#include <math.h>

// Problem constants (fixed by the reference: B=64, P=1024, D=768)
#define Bsz   64
#define Pseq  1024
#define Ddim  768
#define RTOT  (Bsz * Pseq)            // 65536 total rows
#define NCTA  148                     // one CTA per SM, full wave
#define NWARPS 16
#define NTHREADS (NWARPS * 32)        // 512
#define DPL (Ddim / 32)               // 24 d-elements per lane
#define SLOTS (2 * NCTA)              // <=2 batch-partials per CTA

#define QE  16                        // e-rows per qw-partial chunk
#define QNC (Ddim / QE)               // 48 chunks

// Scratch (no cudaMalloc allowed) -------------------------------------------
__device__ float g_qw_part[QNC][Ddim];
__device__ float g_qw[Ddim];
__device__ float g_pm[SLOTS];
__device__ float g_pl[SLOTS];
__device__ int   g_ptag[SLOTS];
__device__ float g_pacc[SLOTS * Ddim];

// Kernel 1a: partial qw, vectorized. grid=QNC, block=192 (each thread owns 4 d)
__global__ void qw_part_kernel(const float* __restrict__ q,
                               const float* __restrict__ W) {
    const int d4 = threadIdx.x * 4;
    const int e0 = blockIdx.x * QE;
    float4 acc = make_float4(0.f, 0.f, 0.f, 0.f);
#pragma unroll
    for (int i = 0; i < QE; ++i) {
        const float qv = __ldg(&q[e0 + i]);
        const float4 w = *reinterpret_cast<const float4*>(&W[(long)(e0 + i) * Ddim + d4]);
        acc.x += qv * w.x; acc.y += qv * w.y;
        acc.z += qv * w.z; acc.w += qv * w.w;
    }
    *reinterpret_cast<float4*>(&g_qw_part[blockIdx.x][d4]) = acc;
}

// Kernel 1b: fold QNC partials into g_qw (L2-hot). grid=1, block=192
__global__ void qw_reduce_kernel() {
    const int d4 = threadIdx.x * 4;
    float4 acc = make_float4(0.f, 0.f, 0.f, 0.f);
#pragma unroll
    for (int c = 0; c < QNC; ++c) {
        const float4 v = *reinterpret_cast<const float4*>(&g_qw_part[c][d4]);
        acc.x += v.x; acc.y += v.y; acc.z += v.z; acc.w += v.w;
    }
    const float s = rsqrtf((float)Ddim);
    acc.x *= s; acc.y *= s; acc.z *= s; acc.w *= s;
    *reinterpret_cast<float4*>(&g_qw[d4]) = acc;
}

// Kernel 2: flattened-row online-softmax partials ------------------------------
// 148 CTAs cover all 65536 rows evenly; each CTA spans <=2 batches and emits
// up to 2 tagged partial states (slots 2*bid, 2*bid+1).
// NO prefetch double-buffer: keeps live floats at 72/thread (no spills).
__device__ __forceinline__ void load_row(const float* __restrict__ zr, int lane,
                                         float v[DPL]) {
#pragma unroll
    for (int i = 0; i < 6; ++i) {
        float4 t = *reinterpret_cast<const float4*>(&zr[i * 128 + lane * 4]);
        v[i * 4 + 0] = t.x; v[i * 4 + 1] = t.y;
        v[i * 4 + 2] = t.z; v[i * 4 + 3] = t.w;
    }
}

extern __shared__ float smem[];
__global__ __launch_bounds__(NTHREADS)
void attn_partial_kernel(const float* __restrict__ z) {
    float* qw_s  = smem;                     // [Ddim]
    float* acc_s = smem + Ddim;              // [NWARPS * Ddim]
    float* m_s   = acc_s + NWARPS * Ddim;    // [NWARPS]
    float* l_s   = m_s + NWARPS;             // [NWARPS]

    const int bid  = blockIdx.x;
    const int tid  = threadIdx.x;
    const int w    = tid >> 5;
    const int lane = tid & 31;

    for (int t = tid; t < Ddim; t += NTHREADS) qw_s[t] = g_qw[t];
    __syncthreads();

    float qw_r[DPL];
    load_row(qw_s, lane, qw_r);

    // This CTA's contiguous row range, split evenly among warps
    const int start = (int)(((long)bid * RTOT) / NCTA);
    const int end   = (int)(((long)(bid + 1) * RTOT) / NCTA);
    const int cnt   = end - start;
    const int ws    = start + (int)(((long)w * cnt) / NWARPS);
    const int we    = start + (int)(((long)(w + 1) * cnt) / NWARPS);
    const int bstart = start >> 10;           // Pseq = 1024 = 2^10
    const int bend   = (end - 1) >> 10;

#pragma unroll 1
    for (int pass = 0; pass < 2; ++pass) {
        int bb = (pass == 0) ? bstart : ((bend != bstart) ? bend : -1);
        int lo = ws, hi = we;
        if (bb >= 0) {
            lo = max(ws, bb << 10);
            hi = min(we, (bb + 1) << 10);
        } else { lo = 0; hi = 0; }

        float m = -INFINITY, l = 0.f;
        float acc[DPL];
#pragma unroll
        for (int j = 0; j < DPL; ++j) acc[j] = 0.f;

        for (int g = lo; g < hi; ++g) {
            float cv[DPL];
            load_row(z + (long)g * Ddim, lane, cv);

            float sc = 0.f;
#pragma unroll
            for (int j = 0; j < DPL; ++j) sc += cv[j] * qw_r[j];
#pragma unroll
            for (int o = 16; o; o >>= 1)
                sc += __shfl_xor_sync(0xffffffffu, sc, o);

            float m_new = fmaxf(m, sc);
            float alpha = __expf(m - m_new);
            float wp    = __expf(sc - m_new);
            l = l * alpha + wp;
#pragma unroll
            for (int j = 0; j < DPL; ++j) acc[j] = acc[j] * alpha + wp * cv[j];
            m = m_new;
        }

        // Stage per-warp state
#pragma unroll
        for (int i = 0; i < 6; ++i) {
            float4 v = make_float4(acc[i * 4 + 0], acc[i * 4 + 1],
                                   acc[i * 4 + 2], acc[i * 4 + 3]);
            *reinterpret_cast<float4*>(&acc_s[w * Ddim + i * 128 + lane * 4]) = v;
        }
        if (lane == 0) { m_s[w] = m; l_s[w] = l; }
        __syncthreads();

        // CTA combine -> global slot 2*bid+pass
        float M = -INFINITY;
#pragma unroll
        for (int ww = 0; ww < NWARPS; ++ww) M = fmaxf(M, m_s[ww]);

        const int slot = 2 * bid + pass;
        if (M == -INFINITY) {
            if (tid == 0) { g_ptag[slot] = -1; g_pm[slot] = 0.f; g_pl[slot] = 1.f; }
        } else {
            float ew[NWARPS];
#pragma unroll
            for (int ww = 0; ww < NWARPS; ++ww) ew[ww] = __expf(m_s[ww] - M);
            for (int t = tid; t < Ddim; t += NTHREADS) {
                float sum = 0.f;
#pragma unroll
                for (int ww = 0; ww < NWARPS; ++ww)
                    sum += ew[ww] * acc_s[ww * Ddim + t];
                g_pacc[slot * Ddim + t] = sum;
            }
            if (tid == 0) {
                float L = 0.f;
#pragma unroll
                for (int ww = 0; ww < NWARPS; ++ww) L += ew[ww] * l_s[ww];
                g_pm[slot] = M; g_pl[slot] = L; g_ptag[slot] = bb;
            }
        }
        __syncthreads();   // protect smem reuse in pass 1
    }
}

// Kernel 3: merge partials per batch. A batch (1024 rows, ~2.3 CTA-ranges)
// overlaps at most ~4 CTAs; the window is computed analytically -> <=12 slot
// checks instead of 296.
__global__ void combine_kernel(float* __restrict__ out) {
    const int b = blockIdx.x;
    const int t = threadIdx.x;  // 0..Ddim-1

    int i0 = (int)(((long)(b << 10) * NCTA) / RTOT) - 1;
    int i1 = (int)(((long)((b + 1) << 10) * NCTA) / RTOT) + 1;
    if (i0 < 0) i0 = 0;
    if (i1 > NCTA - 1) i1 = NCTA - 1;

    __shared__ float sm[16], sl[16];
    __shared__ int   sslot[16];
    __shared__ int   scnt;
    if (t == 0) {
        int c = 0;
        for (int i = i0; i <= i1; ++i) {
#pragma unroll
            for (int p = 0; p < 2; ++p) {
                int s = 2 * i + p;
                if (g_ptag[s] == b) {
                    sslot[c] = s; sm[c] = g_pm[s]; sl[c] = g_pl[s]; ++c;
                }
            }
        }
        scnt = c;
    }
    __syncthreads();

    const int n = scnt;
    float M = -INFINITY;
    for (int k = 0; k < n; ++k) M = fmaxf(M, sm[k]);

    float L = 0.f, num = 0.f;
    for (int k = 0; k < n; ++k) {
        float e = __expf(sm[k] - M);
        L   += e * sl[k];
        num += e * g_pacc[sslot[k] * Ddim + t];
    }
    out[b * Ddim + t] = num / L;
}

// ----------------------------------------------------------------------------
extern "C" void kernel_launch(void* const* d_in, const int* in_sizes, int n_in,
                              void* d_out, int out_size) {
    const float* z = nullptr; const float* q = nullptr; const float* W = nullptr;
    for (int i = 0; i < n_in; ++i) {
        if (in_sizes[i] == Bsz * Pseq * Ddim)      z = (const float*)d_in[i];
        else if (in_sizes[i] == Ddim)              q = (const float*)d_in[i];
        else if (in_sizes[i] == Ddim * Ddim)       W = (const float*)d_in[i];
    }
    float* out = (float*)d_out;

    const int smem_bytes = (Ddim + NWARPS * Ddim + 2 * NWARPS) * (int)sizeof(float);
    cudaFuncSetAttribute(attn_partial_kernel,
                         cudaFuncAttributeMaxDynamicSharedMemorySize, smem_bytes);

    qw_part_kernel<<<QNC, Ddim / 4>>>(q, W);
    qw_reduce_kernel<<<1, Ddim / 4>>>();
    attn_partial_kernel<<<NCTA, NTHREADS, smem_bytes>>>(z);
    combine_kernel<<<Bsz, Ddim>>>(out);
}

// round 5
// speedup vs baseline: 1.5972x; 1.3284x over previous
#include <cuda_runtime.h>
#include <math.h>

// Problem constants (fixed by the reference: B=64, P=1024, D=768)
#define Bsz   64
#define Pseq  1024
#define Ddim  768
#define SPLIT 4                        // CTAs per batch -> 256 CTAs total
#define ROWS_PER_CTA (Pseq / SPLIT)    // 256
#define NWARPS 8
#define NTHREADS (NWARPS * 32)         // 256
#define ROWS_PER_WARP (ROWS_PER_CTA / NWARPS)  // 32 (compile-time!)
#define DPL (Ddim / 32)                // 24 d-elements per lane
#define SLOTS (Bsz * SPLIT)            // 256

#define QE  16                         // e-rows per qw-partial chunk
#define QNC (Ddim / QE)                // 48 chunks

// Scratch (no cudaMalloc allowed) -------------------------------------------
__device__ float g_qw_part[QNC][Ddim];
__device__ float g_qw[Ddim];
__device__ float g_pm[SLOTS];
__device__ float g_pl[SLOTS];
__device__ float g_pacc[SLOTS * Ddim];

// Kernel 1a: partial qw, vectorized. grid=QNC, block=192 (each thread owns 4 d)
__global__ void qw_part_kernel(const float* __restrict__ q,
                               const float* __restrict__ W) {
    const int d4 = threadIdx.x * 4;
    const int e0 = blockIdx.x * QE;
    float4 acc = make_float4(0.f, 0.f, 0.f, 0.f);
#pragma unroll
    for (int i = 0; i < QE; ++i) {
        const float qv = __ldg(&q[e0 + i]);
        const float4 w = *reinterpret_cast<const float4*>(&W[(long)(e0 + i) * Ddim + d4]);
        acc.x += qv * w.x; acc.y += qv * w.y;
        acc.z += qv * w.z; acc.w += qv * w.w;
    }
    *reinterpret_cast<float4*>(&g_qw_part[blockIdx.x][d4]) = acc;
}

// Kernel 1b: fold QNC partials into g_qw (L2-hot). grid=1, block=192
__global__ void qw_reduce_kernel() {
    const int d4 = threadIdx.x * 4;
    float4 acc = make_float4(0.f, 0.f, 0.f, 0.f);
#pragma unroll
    for (int c = 0; c < QNC; ++c) {
        const float4 v = *reinterpret_cast<const float4*>(&g_qw_part[c][d4]);
        acc.x += v.x; acc.y += v.y; acc.z += v.z; acc.w += v.w;
    }
    const float s = rsqrtf((float)Ddim);
    acc.x *= s; acc.y *= s; acc.z *= s; acc.w *= s;
    *reinterpret_cast<float4*>(&g_qw[d4]) = acc;
}

// Kernel 2: per-(batch, quarter) online-softmax pooled partial -----------------
// 256 CTAs x 8 warps, each warp owns exactly 32 contiguous rows (compile-time
// trip count -> ptxas unrolls/pipelines the load stream, high MLP).
__device__ __forceinline__ void load_row(const float* __restrict__ zr, int lane,
                                         float v[DPL]) {
#pragma unroll
    for (int i = 0; i < 6; ++i) {
        float4 t = *reinterpret_cast<const float4*>(&zr[i * 128 + lane * 4]);
        v[i * 4 + 0] = t.x; v[i * 4 + 1] = t.y;
        v[i * 4 + 2] = t.z; v[i * 4 + 3] = t.w;
    }
}

extern __shared__ float smem[];
__global__ __launch_bounds__(NTHREADS, 2)
void attn_partial_kernel(const float* __restrict__ z) {
    float* qw_s  = smem;                     // [Ddim]
    float* acc_s = smem + Ddim;              // [NWARPS * Ddim]
    float* m_s   = acc_s + NWARPS * Ddim;    // [NWARPS]
    float* l_s   = m_s + NWARPS;             // [NWARPS]

    const int bid  = blockIdx.x;             // 0..255 ; batch = bid/SPLIT
    const int tid  = threadIdx.x;
    const int w    = tid >> 5;
    const int lane = tid & 31;

    for (int t = tid; t < Ddim; t += NTHREADS) qw_s[t] = g_qw[t];
    __syncthreads();

    float qw_r[DPL];
    load_row(qw_s, lane, qw_r);

    float m = -INFINITY, l = 0.f;
    float acc[DPL];
#pragma unroll
    for (int j = 0; j < DPL; ++j) acc[j] = 0.f;

    // CTA bid covers rows [bid*256, bid*256+256) of the flattened [B*P] axis;
    // warp w owns 32 of them.
    const float* zb = z + ((long)bid * ROWS_PER_CTA + (long)w * ROWS_PER_WARP) * Ddim;

    for (int r = 0; r < ROWS_PER_WARP; ++r) {
        const float* zr = zb + (long)r * Ddim;
        float cv[DPL];
        load_row(zr, lane, cv);

        float sc = 0.f;
#pragma unroll
        for (int j = 0; j < DPL; ++j) sc += cv[j] * qw_r[j];
#pragma unroll
        for (int o = 16; o; o >>= 1)
            sc += __shfl_xor_sync(0xffffffffu, sc, o);

        float m_new = fmaxf(m, sc);
        float alpha = __expf(m - m_new);   // exp(-inf)=0 on first row: safe
        float wp    = __expf(sc - m_new);
        l = l * alpha + wp;
#pragma unroll
        for (int j = 0; j < DPL; ++j) acc[j] = acc[j] * alpha + wp * cv[j];
        m = m_new;
    }

    // Stage per-warp state to smem
#pragma unroll
    for (int i = 0; i < 6; ++i) {
        float4 v = make_float4(acc[i * 4 + 0], acc[i * 4 + 1],
                               acc[i * 4 + 2], acc[i * 4 + 3]);
        *reinterpret_cast<float4*>(&acc_s[w * Ddim + i * 128 + lane * 4]) = v;
    }
    if (lane == 0) { m_s[w] = m; l_s[w] = l; }
    __syncthreads();

    // Cross-warp combine into one partial per CTA
    float M = -INFINITY;
#pragma unroll
    for (int ww = 0; ww < NWARPS; ++ww) M = fmaxf(M, m_s[ww]);

    float ew[NWARPS];
#pragma unroll
    for (int ww = 0; ww < NWARPS; ++ww) ew[ww] = __expf(m_s[ww] - M);

    for (int t = tid; t < Ddim; t += NTHREADS) {
        float sum = 0.f;
#pragma unroll
        for (int ww = 0; ww < NWARPS; ++ww)
            sum += ew[ww] * acc_s[ww * Ddim + t];
        g_pacc[bid * Ddim + t] = sum;
    }
    if (tid == 0) {
        float L = 0.f;
#pragma unroll
        for (int ww = 0; ww < NWARPS; ++ww) L += ew[ww] * l_s[ww];
        g_pm[bid] = M;
        g_pl[bid] = L;
    }
}

// Kernel 3: merge SPLIT fixed slots per batch (all loads independent) ----------
__global__ void combine_kernel(float* __restrict__ out) {
    const int b = blockIdx.x;
    const int t = threadIdx.x;  // 0..Ddim-1

    float ms[SPLIT], ls[SPLIT];
#pragma unroll
    for (int s = 0; s < SPLIT; ++s) {   // broadcast loads, issued in parallel
        ms[s] = g_pm[b * SPLIT + s];
        ls[s] = g_pl[b * SPLIT + s];
    }
    float M = -INFINITY;
#pragma unroll
    for (int s = 0; s < SPLIT; ++s) M = fmaxf(M, ms[s]);

    float L = 0.f, num = 0.f;
#pragma unroll
    for (int s = 0; s < SPLIT; ++s) {
        float e = __expf(ms[s] - M);
        L   += e * ls[s];
        num += e * g_pacc[(b * SPLIT + s) * Ddim + t];
    }
    out[b * Ddim + t] = num / L;
}

// ----------------------------------------------------------------------------
extern "C" void kernel_launch(void* const* d_in, const int* in_sizes, int n_in,
                              void* d_out, int out_size) {
    const float* z = nullptr; const float* q = nullptr; const float* W = nullptr;
    for (int i = 0; i < n_in; ++i) {
        if (in_sizes[i] == Bsz * Pseq * Ddim)      z = (const float*)d_in[i];
        else if (in_sizes[i] == Ddim)              q = (const float*)d_in[i];
        else if (in_sizes[i] == Ddim * Ddim)       W = (const float*)d_in[i];
    }
    float* out = (float*)d_out;

    const int smem_bytes = (Ddim + NWARPS * Ddim + 2 * NWARPS) * (int)sizeof(float);
    cudaFuncSetAttribute(attn_partial_kernel,
                         cudaFuncAttributeMaxDynamicSharedMemorySize, smem_bytes);

    qw_part_kernel<<<QNC, Ddim / 4>>>(q, W);
    qw_reduce_kernel<<<1, Ddim / 4>>>();
    attn_partial_kernel<<<Bsz * SPLIT, NTHREADS, smem_bytes>>>(z);
    combine_kernel<<<Bsz, Ddim>>>(out);
}

// round 6
// speedup vs baseline: 1.8309x; 1.1463x over previous
#include <cuda_runtime.h>
#include <math.h>

// Problem constants (fixed by the reference: B=64, P=1024, D=768)
#define Bsz   64
#define Pseq  1024
#define Ddim  768
#define SPLIT 4                        // CTAs per batch -> 256 CTAs total
#define ROWS_PER_CTA (Pseq / SPLIT)    // 256
#define NWARPS 8
#define NTHREADS (NWARPS * 32)         // 256
#define ROWS_PER_WARP (ROWS_PER_CTA / NWARPS)  // 32 (compile-time!)
#define DPL (Ddim / 32)                // 24 d-elements per lane
#define SLOTS (Bsz * SPLIT)            // 256

#define QE  16                         // e-rows per qw-partial chunk
#define QNC (Ddim / QE)                // 48 chunks

// Scratch (no cudaMalloc allowed) -------------------------------------------
__device__ float g_qw_part[QNC][Ddim];
__device__ float g_qw[Ddim];
__device__ float g_pm[SLOTS];
__device__ float g_pl[SLOTS];
__device__ float g_pacc[SLOTS * Ddim];

// Kernel 1a: partial qw, vectorized. grid=QNC, block=192 (each thread owns 4 d)
__global__ void qw_part_kernel(const float* __restrict__ q,
                               const float* __restrict__ W) {
    const int d4 = threadIdx.x * 4;
    const int e0 = blockIdx.x * QE;
    float4 acc = make_float4(0.f, 0.f, 0.f, 0.f);
#pragma unroll
    for (int i = 0; i < QE; ++i) {
        const float qv = __ldg(&q[e0 + i]);
        const float4 w = *reinterpret_cast<const float4*>(&W[(long)(e0 + i) * Ddim + d4]);
        acc.x += qv * w.x; acc.y += qv * w.y;
        acc.z += qv * w.z; acc.w += qv * w.w;
    }
    *reinterpret_cast<float4*>(&g_qw_part[blockIdx.x][d4]) = acc;
}

// Kernel 1b: fold QNC partials into g_qw. grid=4, block=192 (1 scalar d each;
// 48 independent loads per thread, fully parallel)
__global__ void qw_reduce_kernel() {
    const int d = blockIdx.x * 192 + threadIdx.x;
    float acc = 0.f;
#pragma unroll
    for (int c = 0; c < QNC; ++c) acc += g_qw_part[c][d];
    g_qw[d] = acc * rsqrtf((float)Ddim);
}

// Kernel 2: per-(batch, quarter) online-softmax pooled partial -----------------
// 256 CTAs x 8 warps, each warp owns exactly 32 contiguous rows, processed in
// PAIRS: two dot/butterfly pipelines overlap, one merged softmax update.
__device__ __forceinline__ void load_row(const float* __restrict__ zr, int lane,
                                         float v[DPL]) {
#pragma unroll
    for (int i = 0; i < 6; ++i) {
        float4 t = *reinterpret_cast<const float4*>(&zr[i * 128 + lane * 4]);
        v[i * 4 + 0] = t.x; v[i * 4 + 1] = t.y;
        v[i * 4 + 2] = t.z; v[i * 4 + 3] = t.w;
    }
}

extern __shared__ float smem[];
__global__ __launch_bounds__(NTHREADS, 2)
void attn_partial_kernel(const float* __restrict__ z) {
    float* qw_s  = smem;                     // [Ddim]
    float* acc_s = smem + Ddim;              // [NWARPS * Ddim]
    float* m_s   = acc_s + NWARPS * Ddim;    // [NWARPS]
    float* l_s   = m_s + NWARPS;             // [NWARPS]

    const int bid  = blockIdx.x;             // 0..255 ; batch = bid/SPLIT
    const int tid  = threadIdx.x;
    const int w    = tid >> 5;
    const int lane = tid & 31;

    for (int t = tid; t < Ddim; t += NTHREADS) qw_s[t] = g_qw[t];
    __syncthreads();

    float qw_r[DPL];
    load_row(qw_s, lane, qw_r);

    float m = -INFINITY, l = 0.f;
    float acc[DPL];
#pragma unroll
    for (int j = 0; j < DPL; ++j) acc[j] = 0.f;

    const float* zb = z + ((long)bid * ROWS_PER_CTA + (long)w * ROWS_PER_WARP) * Ddim;

    for (int r = 0; r < ROWS_PER_WARP; r += 2) {
        float cv0[DPL], cv1[DPL];
        load_row(zb + (long)r * Ddim,       lane, cv0);   // 12 LDG.128
        load_row(zb + (long)(r + 1) * Ddim, lane, cv1);   // back-to-back

        float s0 = 0.f, s1 = 0.f;
#pragma unroll
        for (int j = 0; j < DPL; ++j) { s0 += cv0[j] * qw_r[j]; s1 += cv1[j] * qw_r[j]; }
#pragma unroll
        for (int o = 16; o; o >>= 1) {        // two butterflies, interleaved
            s0 += __shfl_xor_sync(0xffffffffu, s0, o);
            s1 += __shfl_xor_sync(0xffffffffu, s1, o);
        }

        float m_new = fmaxf(m, fmaxf(s0, s1));
        float alpha = __expf(m - m_new);      // exp(-inf)=0 first pair: safe
        float w0    = __expf(s0 - m_new);
        float w1    = __expf(s1 - m_new);
        l = l * alpha + w0 + w1;
#pragma unroll
        for (int j = 0; j < DPL; ++j)
            acc[j] = acc[j] * alpha + w0 * cv0[j] + w1 * cv1[j];
        m = m_new;
    }

    // Stage per-warp state to smem
#pragma unroll
    for (int i = 0; i < 6; ++i) {
        float4 v = make_float4(acc[i * 4 + 0], acc[i * 4 + 1],
                               acc[i * 4 + 2], acc[i * 4 + 3]);
        *reinterpret_cast<float4*>(&acc_s[w * Ddim + i * 128 + lane * 4]) = v;
    }
    if (lane == 0) { m_s[w] = m; l_s[w] = l; }
    __syncthreads();

    // Cross-warp combine into one partial per CTA
    float M = -INFINITY;
#pragma unroll
    for (int ww = 0; ww < NWARPS; ++ww) M = fmaxf(M, m_s[ww]);

    float ew[NWARPS];
#pragma unroll
    for (int ww = 0; ww < NWARPS; ++ww) ew[ww] = __expf(m_s[ww] - M);

    for (int t = tid; t < Ddim; t += NTHREADS) {
        float sum = 0.f;
#pragma unroll
        for (int ww = 0; ww < NWARPS; ++ww)
            sum += ew[ww] * acc_s[ww * Ddim + t];
        g_pacc[bid * Ddim + t] = sum;
    }
    if (tid == 0) {
        float L = 0.f;
#pragma unroll
        for (int ww = 0; ww < NWARPS; ++ww) L += ew[ww] * l_s[ww];
        g_pm[bid] = M;
        g_pl[bid] = L;
    }
}

// Kernel 3: merge SPLIT fixed slots per batch. 256 CTAs x 192 threads:
// block (b, quarter) writes 192 of batch b's 768 outputs. All loads independent.
__global__ void combine_kernel(float* __restrict__ out) {
    const int b = blockIdx.x >> 2;
    const int t = (blockIdx.x & 3) * 192 + threadIdx.x;

    float ms[SPLIT], ls[SPLIT];
#pragma unroll
    for (int s = 0; s < SPLIT; ++s) {
        ms[s] = g_pm[b * SPLIT + s];
        ls[s] = g_pl[b * SPLIT + s];
    }
    float M = -INFINITY;
#pragma unroll
    for (int s = 0; s < SPLIT; ++s) M = fmaxf(M, ms[s]);

    float L = 0.f, num = 0.f;
#pragma unroll
    for (int s = 0; s < SPLIT; ++s) {
        float e = __expf(ms[s] - M);
        L   += e * ls[s];
        num += e * g_pacc[(b * SPLIT + s) * Ddim + t];
    }
    out[b * Ddim + t] = num / L;
}

// ----------------------------------------------------------------------------
extern "C" void kernel_launch(void* const* d_in, const int* in_sizes, int n_in,
                              void* d_out, int out_size) {
    const float* z = nullptr; const float* q = nullptr; const float* W = nullptr;
    for (int i = 0; i < n_in; ++i) {
        if (in_sizes[i] == Bsz * Pseq * Ddim)      z = (const float*)d_in[i];
        else if (in_sizes[i] == Ddim)              q = (const float*)d_in[i];
        else if (in_sizes[i] == Ddim * Ddim)       W = (const float*)d_in[i];
    }
    float* out = (float*)d_out;

    const int smem_bytes = (Ddim + NWARPS * Ddim + 2 * NWARPS) * (int)sizeof(float);
    cudaFuncSetAttribute(attn_partial_kernel,
                         cudaFuncAttributeMaxDynamicSharedMemorySize, smem_bytes);

    qw_part_kernel<<<QNC, Ddim / 4>>>(q, W);
    qw_reduce_kernel<<<4, 192>>>();
    attn_partial_kernel<<<Bsz * SPLIT, NTHREADS, smem_bytes>>>(z);
    combine_kernel<<<Bsz * SPLIT, 192>>>(out);
}